// round 15
// baseline (speedup 1.0000x reference)
#include <cuda_runtime.h>
#include <cstdint>
#include <math.h>

#define N_NODES 65536
#define N_EDGES 1048576
#define N_GRAPHS 256

// ===================== device scratch =====================
__device__ __align__(16) float g_out[N_NODES * 64];        // node state h/out
__device__ __align__(16) float g_gx[N_NODES * 192];        // x @ Wx^T + b_ih (loop invariant)
__device__ __align__(16) float g_m0[N_NODES * 64];         // gather-sum of out[src]
__device__ __align__(16) float g_gg[N_NODES * 256];        // fused GEMM out (r,z,gi_n,gh_n)
__device__ __align__(16) float g_e[N_NODES];               // attention logits / weights

__device__ __align__(16) float g_W0hi[256 * 32];           // [W_mlp ; Wx] tf32-hi
__device__ __align__(16) float g_W0lo[256 * 32];
__device__ __align__(16) float g_b0[256];
__device__ __align__(16) float g_Wbhi[256 * 128];          // fused step weights tf32-hi
__device__ __align__(16) float g_Wblo[256 * 128];
__device__ __align__(16) float g_bmc[192];                 // Wm @ b_conv
__device__ __align__(16) float g_bzero[256];
__device__ __align__(16) float g_WlT[192 * 256];           // LSTM [W_ih|W_hh] k-major
__device__ __align__(16) float g_bl[256];

__device__ __align__(16) float g_qs[N_GRAPHS * 128];
__device__ __align__(16) float g_hl[N_GRAPHS * 64];
__device__ __align__(16) float g_cl[N_GRAPHS * 64];

__device__ __align__(16) int g_cnt[N_NODES];
__device__ __align__(16) int g_rowptr[N_NODES + 1];
__device__ __align__(16) int g_cursor[N_NODES];
__device__ __align__(16) int g_csrc[N_EDGES];
__device__ __align__(16) int g_bsum[256];
__device__ __align__(16) int g_boff[256];

__device__ int g_seg[N_GRAPHS + 1];
__device__ int g_is64;

// ===================== helpers =====================
__device__ __forceinline__ uint32_t f2tf32(float x) {
    uint32_t r;
    asm("cvt.rna.tf32.f32 %0, %1;" : "=r"(r) : "f"(x));
    return r;
}

// m16n8k8 tf32 warp mma, D += A*B (arch-neutral PTX, works on compute_103 base)
#define MMA_TF32(c, a, b) \
    asm volatile("mma.sync.aligned.m16n8k8.row.col.f32.tf32.tf32.f32 " \
        "{%0,%1,%2,%3}, {%4,%5,%6,%7}, {%8,%9}, {%0,%1,%2,%3};" \
        : "+f"((c)[0]), "+f"((c)[1]), "+f"((c)[2]), "+f"((c)[3]) \
        : "r"((a)[0]), "r"((a)[1]), "r"((a)[2]), "r"((a)[3]), \
          "r"((b)[0]), "r"((b)[1]))

// ===================== setup kernels =====================
// grid 256x256: zero g_cnt (65536 ints); block 0 additionally detects int64 indices
__global__ void k_detect(const int* __restrict__ ei) {
    int t = blockIdx.x * 256 + threadIdx.x;
    g_cnt[t] = 0;
    if (blockIdx.x == 0) {
        __shared__ int any;
        if (threadIdx.x == 0) any = 0;
        __syncthreads();
        for (int i = threadIdx.x; i < 2048; i += 256)
            if (ei[2 * i + 1] != 0) any = 1;
        __syncthreads();
        if (threadIdx.x == 0) g_is64 = (any == 0) ? 1 : 0;
    }
}

// grid 4096x256 (1M threads): histogram by dst; first 64K threads also build seg[]
__global__ void k_seghist(const int* __restrict__ ei, const int* __restrict__ batch) {
    int e = blockIdx.x * 256 + threadIdx.x;
    int is64 = g_is64;
    int dst = is64 ? ei[2 * (N_EDGES + e)] : ei[N_EDGES + e];
    atomicAdd(&g_cnt[dst], 1);
    if (e < N_NODES) {
        int i = e;
        int b  = batch[is64 ? 2 * i : i];
        int pb = (i == 0) ? -1 : batch[is64 ? 2 * (i - 1) : (i - 1)];
        for (int g = pb + 1; g <= b; ++g) g_seg[g] = i;
        if (i == N_NODES - 1)
            for (int g = b + 1; g <= N_GRAPHS; ++g) g_seg[g] = N_NODES;
    }
}

// ===================== weight packing =====================
// Wbig rows: [0:64) r: [Wmc_r | Whh_r]; [64:128) z; [128:192) gi_n: [Wmc_n | 0];
// [192:256) gh_n: [0 | Whh_n].   Wmc = Wih[:, :64] @ W_conv  (linearity fold)
__global__ void k_pack(const float* __restrict__ Wmlp, const float* __restrict__ bmlp,
                       const float* __restrict__ gWih, const float* __restrict__ gbih,
                       const float* __restrict__ Wconv, const float* __restrict__ bconv,
                       const float* __restrict__ gWhh,
                       const float* __restrict__ lWih, const float* __restrict__ lWhh,
                       const float* __restrict__ lbih, const float* __restrict__ lbhh) {
    int t0 = blockIdx.x * blockDim.x + threadIdx.x;
    int st = gridDim.x * blockDim.x;
    for (int t = t0; t < 256 * 32; t += st) {
        int o = t >> 5, k = t & 31;
        float v = (o < 64) ? Wmlp[o * 32 + k] : gWih[(o - 64) * 96 + 64 + k];
        float hi = __uint_as_float(f2tf32(v));
        g_W0hi[t] = hi;
        g_W0lo[t] = __uint_as_float(f2tf32(v - hi));
    }
    for (int t = t0; t < 256; t += st)
        g_b0[t] = (t < 64) ? bmlp[t] : gbih[t - 64];
    for (int t = t0; t < 256 * 128; t += st) {
        int o = t >> 7, k = t & 127;
        float v;
        if (k < 64) {
            if (o < 192) {
                float a = 0.f;
#pragma unroll 8
                for (int j = 0; j < 64; j++) a += gWih[o * 96 + j] * Wconv[j * 64 + k];
                v = a;
            } else v = 0.f;
        } else {
            if (o < 128)      v = gWhh[o * 64 + (k - 64)];
            else if (o < 192) v = 0.f;
            else              v = gWhh[(o - 64) * 64 + (k - 64)];
        }
        float hi = __uint_as_float(f2tf32(v));
        g_Wbhi[t] = hi;
        g_Wblo[t] = __uint_as_float(f2tf32(v - hi));
    }
    for (int t = t0; t < 192; t += st) {
        float a = 0.f;
#pragma unroll 8
        for (int j = 0; j < 64; j++) a += gWih[t * 96 + j] * bconv[j];
        g_bmc[t] = a;
    }
    for (int t = t0; t < 256; t += st) g_bzero[t] = 0.f;
    // LSTM weights, k-major: WlT[k][o], k in [0,192) over [q_star | hl]
    for (int t = t0; t < 192 * 256; t += st) {
        int k = t >> 8, o = t & 255;
        g_WlT[t] = (k < 128) ? lWih[o * 128 + k] : lWhh[o * 64 + (k - 128)];
    }
    for (int t = t0; t < 256; t += st) g_bl[t] = lbih[t] + lbhh[t];
}

// ===================== parallel CSR scan =====================
__global__ void k_scanA() {            // grid 256x256: block sums of cnt
    __shared__ int red[256];
    int b = blockIdx.x, t = threadIdx.x;
    red[t] = g_cnt[b * 256 + t];
    __syncthreads();
    for (int off = 128; off > 0; off >>= 1) {
        if (t < off) red[t] += red[t + off];
        __syncthreads();
    }
    if (t == 0) g_bsum[b] = red[0];
}

__global__ void k_scanB() {            // 1 block x256: exclusive scan of block sums
    __shared__ int part[256];
    int t = threadIdx.x;
    int v = g_bsum[t];
    part[t] = v;
    __syncthreads();
    for (int off = 1; off < 256; off <<= 1) {
        int u = (t >= off) ? part[t - off] : 0;
        __syncthreads();
        part[t] += u;
        __syncthreads();
    }
    g_boff[t] = part[t] - v;           // exclusive
}

__global__ void k_scanC() {            // grid 256x256: local scan + offset -> rowptr/cursor
    __shared__ int part[256];
    int b = blockIdx.x, t = threadIdx.x;
    int c = g_cnt[b * 256 + t];
    part[t] = c;
    __syncthreads();
    for (int off = 1; off < 256; off <<= 1) {
        int u = (t >= off) ? part[t - off] : 0;
        __syncthreads();
        part[t] += u;
        __syncthreads();
    }
    int excl = g_boff[b] + part[t] - c;
    g_rowptr[b * 256 + t] = excl;
    g_cursor[b * 256 + t] = excl;
    if (b == 255 && t == 255) g_rowptr[N_NODES] = excl + c;
}

__global__ void k_fill(const int* __restrict__ ei) {
    int e = blockIdx.x * 256 + threadIdx.x;
    int src, dst;
    if (g_is64) { src = ei[2 * e]; dst = ei[2 * (N_EDGES + e)]; }
    else        { src = ei[e];     dst = ei[N_EDGES + e]; }
    int pos = atomicAdd(&g_cursor[dst], 1);
    g_csrc[pos] = src;
}

// m0[n] = sum over in-edges of out[src], order-independent via int64 fixed-point
#define FPSCALE   1099511627776.f      // 2^40
#define FPINV     9.094947017729282e-13f
__global__ void k_gather() {
    unsigned t = blockIdx.x * 256u + threadIdx.x;   // N*16 threads
    int n = t >> 4, c = t & 15;
    int beg = g_rowptr[n], end = g_rowptr[n + 1];
    const float4* o4 = reinterpret_cast<const float4*>(g_out);
    long long ax = 0, ay = 0, az = 0, aw = 0;
#pragma unroll 4
    for (int i = beg; i < end; i++) {
        int s = g_csrc[i];
        float4 v = o4[s * 16 + c];
        ax += __float2ll_rn(v.x * FPSCALE);
        ay += __float2ll_rn(v.y * FPSCALE);
        az += __float2ll_rn(v.z * FPSCALE);
        aw += __float2ll_rn(v.w * FPSCALE);
    }
    float4 acc;
    acc.x = (float)ax * FPINV;
    acc.y = (float)ay * FPINV;
    acc.z = (float)az * FPINV;
    acc.w = (float)aw * FPINV;
    reinterpret_cast<float4*>(g_m0)[n * 16 + c] = acc;
}

// ===================== tensor-core GEMM: mma.sync tf32, 3x split =====================
// C[65536, 256] = concat(A0[:, :aw], A1)[M, NC*32] @ W[256, NC*32]^T + bias
// CTA tile 128x64, 8 warps as 4(m) x 2(n), warp tile 32x32 (2 m16 x 4 n8).
// smem row stride 36 (== 4 mod 32 -> fragment LDS conflict-free).
// __launch_bounds__(256, 4): force regs<=64 so 4 CTAs/SM fit (was reg-limited to 3).
template <int NC>
__global__ void __launch_bounds__(256, 4) k_mma(
    const float* __restrict__ A0, const float* __restrict__ A1, int aw,
    const float* __restrict__ Whi, const float* __restrict__ Wlo, int wstride,
    const float* __restrict__ bias,
    float* __restrict__ d1, float* __restrict__ d2, int split, int ld1, int ld2) {
    constexpr int KC = 32, KCp = 36;
    extern __shared__ float sm[];
    float* Ah = sm;                      // [128][36]
    float* Al = Ah + 128 * KCp;
    float* Wh = Al + 128 * KCp;          // [64][36]
    float* Wl = Wh + 64 * KCp;

    const int tid = threadIdx.x;
    const int lane = tid & 31, wid = tid >> 5;
    const int wm = wid >> 1, wn = wid & 1;
    const int r0 = blockIdx.x * 128;
    const int c0 = blockIdx.y * 64;
    const int gq = lane >> 2, tg = lane & 3;

    float acc[2][4][4];
#pragma unroll
    for (int mt = 0; mt < 2; mt++)
#pragma unroll
        for (int nt = 0; nt < 4; nt++)
#pragma unroll
            for (int j = 0; j < 4; j++) acc[mt][nt][j] = 0.f;

    for (int ch = 0; ch < NC; ch++) {
        const int off = ch * KC;
        const float* S;
        int w, soff;
        if (off < aw) { S = A0; w = aw; soff = off; }
        else          { S = A1; w = NC * 32 - aw; soff = off - aw; }
        // stage A chunk, convert fp32 -> tf32 hi/lo
        for (int i4 = tid; i4 < 128 * 8; i4 += 256) {
            int r = i4 >> 3, q = i4 & 7;
            float4 v = *reinterpret_cast<const float4*>(&S[(size_t)(r0 + r) * w + soff + q * 4]);
            float* ph = &Ah[r * KCp + q * 4];
            float* pl = &Al[r * KCp + q * 4];
            float h0 = __uint_as_float(f2tf32(v.x));
            float h1 = __uint_as_float(f2tf32(v.y));
            float h2 = __uint_as_float(f2tf32(v.z));
            float h3 = __uint_as_float(f2tf32(v.w));
            ph[0] = h0; ph[1] = h1; ph[2] = h2; ph[3] = h3;
            pl[0] = __uint_as_float(f2tf32(v.x - h0));
            pl[1] = __uint_as_float(f2tf32(v.y - h1));
            pl[2] = __uint_as_float(f2tf32(v.z - h2));
            pl[3] = __uint_as_float(f2tf32(v.w - h3));
        }
        // stage W chunk (pre-split hi/lo in gmem)
        for (int i4 = tid; i4 < 64 * 8; i4 += 256) {
            int o = i4 >> 3, q = i4 & 7;
            size_t gi = (size_t)(c0 + o) * wstride + off + q * 4;
            float4 vh = *reinterpret_cast<const float4*>(&Whi[gi]);
            float4 vl = *reinterpret_cast<const float4*>(&Wlo[gi]);
            float* ph = &Wh[o * KCp + q * 4];
            float* pl = &Wl[o * KCp + q * 4];
            ph[0] = vh.x; ph[1] = vh.y; ph[2] = vh.z; ph[3] = vh.w;
            pl[0] = vl.x; pl[1] = vl.y; pl[2] = vl.z; pl[3] = vl.w;
        }
        __syncthreads();

#pragma unroll
        for (int kk = 0; kk < KC; kk += 8) {
            uint32_t ah[2][4], al[2][4], bh[4][2], bl[4][2];
#pragma unroll
            for (int mt = 0; mt < 2; mt++) {
                int rb = wm * 32 + mt * 16 + gq;
                const float* pa = &Ah[rb * KCp + kk + tg];
                const float* pl = &Al[rb * KCp + kk + tg];
                ah[mt][0] = __float_as_uint(pa[0]);
                ah[mt][1] = __float_as_uint(pa[8 * KCp]);
                ah[mt][2] = __float_as_uint(pa[4]);
                ah[mt][3] = __float_as_uint(pa[8 * KCp + 4]);
                al[mt][0] = __float_as_uint(pl[0]);
                al[mt][1] = __float_as_uint(pl[8 * KCp]);
                al[mt][2] = __float_as_uint(pl[4]);
                al[mt][3] = __float_as_uint(pl[8 * KCp + 4]);
            }
#pragma unroll
            for (int nt = 0; nt < 4; nt++) {
                int cb = wn * 32 + nt * 8 + gq;
                const float* pb = &Wh[cb * KCp + kk + tg];
                const float* pq = &Wl[cb * KCp + kk + tg];
                bh[nt][0] = __float_as_uint(pb[0]);
                bh[nt][1] = __float_as_uint(pb[4]);
                bl[nt][0] = __float_as_uint(pq[0]);
                bl[nt][1] = __float_as_uint(pq[4]);
            }
#pragma unroll
            for (int mt = 0; mt < 2; mt++)
#pragma unroll
                for (int nt = 0; nt < 4; nt++) {
                    MMA_TF32(acc[mt][nt], ah[mt], bh[nt]);
                    MMA_TF32(acc[mt][nt], al[mt], bh[nt]);
                    MMA_TF32(acc[mt][nt], ah[mt], bl[nt]);
                }
        }
        __syncthreads();
    }

    // epilogue: c0=(g,2tg) c1=(g,2tg+1) c2=(g+8,2tg) c3=(g+8,2tg+1)
#pragma unroll
    for (int mt = 0; mt < 2; mt++) {
        int row0 = r0 + wm * 32 + mt * 16 + gq;
#pragma unroll
        for (int nt = 0; nt < 4; nt++) {
            int col = c0 + wn * 32 + nt * 8 + 2 * tg;
            float b0v = bias[col], b1v = bias[col + 1];
            float2 v0 = make_float2(acc[mt][nt][0] + b0v, acc[mt][nt][1] + b1v);
            float2 v1 = make_float2(acc[mt][nt][2] + b0v, acc[mt][nt][3] + b1v);
            if (col < split) {
                *reinterpret_cast<float2*>(&d1[(size_t)row0 * ld1 + col]) = v0;
                *reinterpret_cast<float2*>(&d1[(size_t)(row0 + 8) * ld1 + col]) = v1;
            } else {
                *reinterpret_cast<float2*>(&d2[(size_t)row0 * ld2 + (col - split)]) = v0;
                *reinterpret_cast<float2*>(&d2[(size_t)(row0 + 8) * ld2 + (col - split)]) = v1;
            }
        }
    }
}

// ===================== GRU elementwise =====================
__global__ void k_gru(const float* __restrict__ bhh) {
    int t = blockIdx.x * 256 + threadIdx.x;     // N*64 threads
    int n = t >> 6, j = t & 63;
    float deg = (float)(g_rowptr[n + 1] - g_rowptr[n]);
    const float* gg = g_gg + (size_t)n * 256;
    const float* gx = g_gx + (size_t)n * 192;
    float rpre = gg[j]       + gx[j]       + deg * g_bmc[j]       + bhh[j];
    float zpre = gg[64 + j]  + gx[64 + j]  + deg * g_bmc[64 + j]  + bhh[64 + j];
    float ginn = gg[128 + j] + gx[128 + j] + deg * g_bmc[128 + j];
    float ghnn = gg[192 + j] + bhh[128 + j];
    float r = 1.f / (1.f + expf(-rpre));
    float z = 1.f / (1.f + expf(-zpre));
    float ng = tanhf(ginn + r * ghnn);
    g_out[t] = (1.f - z) * ng + z * g_out[t];
}

// ===================== fused Set2Set iteration =====================
// block per graph: LSTM gates (k-major W, coalesced) + combine + segmented
// softmax attention + q_star write. first=1 treats q_star/hl/cl as zero.
__global__ void __launch_bounds__(256) k_s2s(const float* __restrict__ WlT,
                                             const float* __restrict__ bl, int first) {
    int g = blockIdx.x;
    int tid = threadIdx.x, lane = tid & 31, warp = tid >> 5;
    __shared__ float sq[192];
    __shared__ float sg[256];
    __shared__ float sh[64];
    __shared__ float sred[8];
    __shared__ float rsm[8][64];

    if (tid < 192)
        sq[tid] = first ? 0.f
                        : (tid < 128 ? g_qs[g * 128 + tid] : g_hl[g * 64 + (tid - 128)]);
    __syncthreads();

    // LSTM gates: thread tid computes gate 'tid' over K=192 (coalesced WlT rows)
    float acc = bl[tid];
#pragma unroll 16
    for (int k = 0; k < 192; k++) acc += sq[k] * WlT[k * 256 + tid];
    sg[tid] = acc;
    __syncthreads();

    // combine (PyTorch gate order i,f,g,o)
    if (tid < 64) {
        float gi = sg[tid], gf = sg[64 + tid], gg = sg[128 + tid], go = sg[192 + tid];
        float cp = first ? 0.f : g_cl[g * 64 + tid];
        float c = 1.f / (1.f + expf(-gf)) * cp + 1.f / (1.f + expf(-gi)) * tanhf(gg);
        g_cl[g * 64 + tid] = c;
        float h = 1.f / (1.f + expf(-go)) * tanhf(c);
        g_hl[g * 64 + tid] = h;
        sh[tid] = h;
    }
    __syncthreads();

    // segmented softmax attention with q = sh
    int n0 = g_seg[g], n1 = g_seg[g + 1];
    float q0 = sh[lane], q1 = sh[lane + 32];
    float wmax = -3.402823466e38f;
    for (int i = n0 + warp; i < n1; i += 8) {
        float p = g_out[i * 64 + lane] * q0 + g_out[i * 64 + 32 + lane] * q1;
#pragma unroll
        for (int s = 16; s > 0; s >>= 1) p += __shfl_xor_sync(0xffffffffu, p, s);
        if (lane == 0) g_e[i] = p;
        wmax = fmaxf(wmax, p);
    }
    if (lane == 0) sred[warp] = wmax;
    __syncthreads();
    if (tid == 0) {
        float m2 = -3.402823466e38f;
        for (int w = 0; w < 8; w++) m2 = fmaxf(m2, sred[w]);
        sred[0] = m2;
    }
    __syncthreads();
    float emax = sred[0];
    __syncthreads();
    float s = 0.f;
    for (int i = n0 + tid; i < n1; i += 256) {
        float v = expf(g_e[i] - emax);
        g_e[i] = v;
        s += v;
    }
#pragma unroll
    for (int sh2 = 16; sh2 > 0; sh2 >>= 1) s += __shfl_xor_sync(0xffffffffu, s, sh2);
    if (lane == 0) sred[warp] = s;
    __syncthreads();
    if (tid == 0) {
        float t2 = 0.f;
        for (int w = 0; w < 8; w++) t2 += sred[w];
        sred[0] = t2;
    }
    __syncthreads();
    float asum = sred[0];
    float r0 = 0.f, r1 = 0.f;
    for (int i = n0 + warp; i < n1; i += 8) {
        float a = g_e[i];
        r0 += a * g_out[i * 64 + lane];
        r1 += a * g_out[i * 64 + 32 + lane];
    }
    rsm[warp][lane] = r0;
    rsm[warp][lane + 32] = r1;
    __syncthreads();
    float inv = 1.f / fmaxf(asum, 1e-16f);
    if (tid < 64) {
        float a2 = 0.f;
        for (int w = 0; w < 8; w++) a2 += rsm[w][tid];
        g_qs[g * 128 + 64 + tid] = a2 * inv;
    } else if (tid < 128) {
        g_qs[g * 128 + (tid - 64)] = sh[tid - 64];
    }
}

// ===================== head =====================
__global__ void __launch_bounds__(128) k_head(const float* __restrict__ W1,
                                              const float* __restrict__ b1,
                                              const float* __restrict__ W2,
                                              const float* __restrict__ b2,
                                              float* __restrict__ outp) {
    __shared__ float sW1[64 * 128];
    __shared__ float sW2[4 * 64];
    __shared__ float sq[128];
    __shared__ float hid[64];
    __shared__ float lg[4];
    int g = blockIdx.x, tid = threadIdx.x;
    for (int i = tid; i < 64 * 128; i += 128) sW1[i] = W1[i];
    for (int i = tid; i < 256; i += 128) sW2[i] = W2[i];
    sq[tid] = g_qs[g * 128 + tid];
    __syncthreads();
    if (tid < 64) {
        float acc = b1[tid];
#pragma unroll 8
        for (int k = 0; k < 128; k++) acc += sq[k] * sW1[tid * 128 + k];
        hid[tid] = fmaxf(acc, 0.f);
    }
    __syncthreads();
    if (tid < 4) {
        float acc = b2[tid];
#pragma unroll
        for (int k = 0; k < 64; k++) acc += hid[k] * sW2[tid * 64 + k];
        lg[tid] = acc;
    }
    __syncthreads();
    if (tid == 0) {
        float m = fmaxf(fmaxf(lg[0], lg[1]), fmaxf(lg[2], lg[3]));
        float sum = expf(lg[0] - m) + expf(lg[1] - m) + expf(lg[2] - m) + expf(lg[3] - m);
        float l = m + logf(sum);
        outp[g * 4 + 0] = lg[0] - l;
        outp[g * 4 + 1] = lg[1] - l;
        outp[g * 4 + 2] = lg[2] - l;
        outp[g * 4 + 3] = lg[3] - l;
    }
}

// ===================== launcher =====================
extern "C" void kernel_launch(void* const* d_in, const int* in_sizes, int n_in,
                              void* d_out, int out_size) {
    const float* x      = (const float*)d_in[0];
    const int*   ei     = (const int*)d_in[1];
    const int*   batch  = (const int*)d_in[2];
    const float* W_mlp  = (const float*)d_in[3];
    const float* b_mlp  = (const float*)d_in[4];
    const float* W_conv = (const float*)d_in[5];
    const float* b_conv = (const float*)d_in[6];
    const float* gWih   = (const float*)d_in[7];
    const float* gWhh   = (const float*)d_in[8];
    const float* gbih   = (const float*)d_in[9];
    const float* gbhh   = (const float*)d_in[10];
    const float* lWih   = (const float*)d_in[11];
    const float* lWhh   = (const float*)d_in[12];
    const float* lbih   = (const float*)d_in[13];
    const float* lbhh   = (const float*)d_in[14];
    const float* W1     = (const float*)d_in[15];
    const float* b1     = (const float*)d_in[16];
    const float* W2     = (const float*)d_in[17];
    const float* b2     = (const float*)d_in[18];

    float *p_out, *p_gx, *p_m0, *p_gg;
    float *p_W0hi, *p_W0lo, *p_b0, *p_Wbhi, *p_Wblo, *p_bzero, *p_WlT, *p_bl;
    cudaGetSymbolAddress((void**)&p_out, g_out);
    cudaGetSymbolAddress((void**)&p_gx, g_gx);
    cudaGetSymbolAddress((void**)&p_m0, g_m0);
    cudaGetSymbolAddress((void**)&p_gg, g_gg);
    cudaGetSymbolAddress((void**)&p_W0hi, g_W0hi);
    cudaGetSymbolAddress((void**)&p_W0lo, g_W0lo);
    cudaGetSymbolAddress((void**)&p_b0, g_b0);
    cudaGetSymbolAddress((void**)&p_Wbhi, g_Wbhi);
    cudaGetSymbolAddress((void**)&p_Wblo, g_Wblo);
    cudaGetSymbolAddress((void**)&p_bzero, g_bzero);
    cudaGetSymbolAddress((void**)&p_WlT, g_WlT);
    cudaGetSymbolAddress((void**)&p_bl, g_bl);

    const int MMA_SMEM = (128 + 128 + 64 + 64) * 36 * 4;   // 55296 B
    cudaFuncSetAttribute((const void*)k_mma<1>, cudaFuncAttributeMaxDynamicSharedMemorySize, MMA_SMEM);
    cudaFuncSetAttribute((const void*)k_mma<4>, cudaFuncAttributeMaxDynamicSharedMemorySize, MMA_SMEM);

    // static side stream + events for graph-captured fork/join (created once;
    // no device memory involved). CSR build overlaps pack + init GEMM.
    static cudaStream_t s1 = nullptr;
    static cudaEvent_t ev_fork = nullptr, ev_join = nullptr;
    if (!s1) {
        cudaStreamCreateWithFlags(&s1, cudaStreamNonBlocking);
        cudaEventCreateWithFlags(&ev_fork, cudaEventDisableTiming);
        cudaEventCreateWithFlags(&ev_join, cudaEventDisableTiming);
    }

    // launch 0: cnt zero + dtype detect (needed by both branches)
    k_detect<<<256, 256>>>(ei);
    cudaEventRecord(ev_fork, 0);
    cudaStreamWaitEvent(s1, ev_fork, 0);

    // side stream: CSR build chain (independent of weights/GEMM)
    k_seghist<<<N_EDGES / 256, 256, 0, s1>>>(ei, batch);
    k_scanA<<<256, 256, 0, s1>>>();
    k_scanB<<<1, 256, 0, s1>>>();
    k_scanC<<<256, 256, 0, s1>>>();
    k_fill<<<N_EDGES / 256, 256, 0, s1>>>(ei);
    cudaEventRecord(ev_join, s1);

    // main stream: weight pack + init GEMM
    k_pack<<<128, 256>>>(W_mlp, b_mlp, gWih, gbih, W_conv, b_conv, gWhh,
                         lWih, lWhh, lbih, lbhh);
    // [out | gx] = x @ [W_mlp ; Wx]^T + [b_mlp ; b_ih]
    k_mma<1><<<dim3(512, 4), 256, MMA_SMEM>>>(x, x, 32, p_W0hi, p_W0lo, 32, p_b0,
                                              p_out, p_gx, 64, 64, 192);

    // join: gather needs CSR (side) + out (main)
    cudaStreamWaitEvent(0, ev_join, 0);

    for (int s = 0; s < 2; s++) {
        k_gather<<<N_NODES * 16 / 256, 256>>>();
        k_mma<4><<<dim3(512, 4), 256, MMA_SMEM>>>(p_m0, p_out, 64, p_Wbhi, p_Wblo, 128,
                                                  p_bzero, p_gg, p_gg, 256, 256, 256);
        k_gru<<<N_NODES * 64 / 256, 256>>>(gbhh);
    }

    // fused Set2Set: 3 launches, no zero-init kernels (first flag)
    k_s2s<<<256, 256>>>(p_WlT, p_bl, 1);
    k_s2s<<<256, 256>>>(p_WlT, p_bl, 0);
    k_s2s<<<256, 256>>>(p_WlT, p_bl, 0);

    k_head<<<256, 128>>>(W1, b1, W2, b2, (float*)d_out);
}

// round 16
// speedup vs baseline: 1.4325x; 1.4325x over previous
#include <cuda_runtime.h>
#include <cstdint>
#include <math.h>

#define N_NODES 65536
#define N_EDGES 1048576
#define N_GRAPHS 256

// ===================== device scratch =====================
__device__ __align__(16) float g_out[N_NODES * 64];        // node state h/out
__device__ __align__(16) float g_gx[N_NODES * 192];        // x @ Wx^T + b_ih (loop invariant)
__device__ __align__(16) float g_m0[N_NODES * 64];         // gather-sum of out[src]
__device__ __align__(16) float g_gg[N_NODES * 256];        // fused GEMM out (r,z,gi_n,gh_n)
__device__ __align__(16) float g_e[N_NODES];               // attention logits / weights

__device__ __align__(16) float g_W0hi[256 * 32];           // [W_mlp ; Wx] tf32-hi
__device__ __align__(16) float g_W0lo[256 * 32];
__device__ __align__(16) float g_b0[256];
__device__ __align__(16) float g_Wbhi[256 * 128];          // fused step weights tf32-hi
__device__ __align__(16) float g_Wblo[256 * 128];
__device__ __align__(16) float g_bmc[192];                 // Wm @ b_conv
__device__ __align__(16) float g_bzero[256];
__device__ __align__(16) float g_WlT[192 * 256];           // LSTM [W_ih|W_hh] k-major
__device__ __align__(16) float g_bl[256];

__device__ __align__(16) float g_qs[N_GRAPHS * 128];
__device__ __align__(16) float g_hl[N_GRAPHS * 64];
__device__ __align__(16) float g_cl[N_GRAPHS * 64];

__device__ __align__(16) int g_cnt[N_NODES];
__device__ __align__(16) int g_rowptr[N_NODES + 1];
__device__ __align__(16) int g_cursor[N_NODES];
__device__ __align__(16) int g_csrc[N_EDGES];
__device__ __align__(16) int g_bsum[256];
__device__ __align__(16) int g_boff[256];

__device__ int g_seg[N_GRAPHS + 1];
__device__ int g_is64;

// ===================== helpers =====================
__device__ __forceinline__ uint32_t f2tf32(float x) {
    uint32_t r;
    asm("cvt.rna.tf32.f32 %0, %1;" : "=r"(r) : "f"(x));
    return r;
}

// m16n8k8 tf32 warp mma, D += A*B (arch-neutral PTX, works on compute_103 base)
#define MMA_TF32(c, a, b) \
    asm volatile("mma.sync.aligned.m16n8k8.row.col.f32.tf32.tf32.f32 " \
        "{%0,%1,%2,%3}, {%4,%5,%6,%7}, {%8,%9}, {%0,%1,%2,%3};" \
        : "+f"((c)[0]), "+f"((c)[1]), "+f"((c)[2]), "+f"((c)[3]) \
        : "r"((a)[0]), "r"((a)[1]), "r"((a)[2]), "r"((a)[3]), \
          "r"((b)[0]), "r"((b)[1]))

// ===================== setup kernels =====================
// grid 256x256: zero g_cnt (65536 ints); block 0 additionally detects int64 indices
__global__ void k_detect(const int* __restrict__ ei) {
    int t = blockIdx.x * 256 + threadIdx.x;
    g_cnt[t] = 0;
    if (blockIdx.x == 0) {
        __shared__ int any;
        if (threadIdx.x == 0) any = 0;
        __syncthreads();
        for (int i = threadIdx.x; i < 2048; i += 256)
            if (ei[2 * i + 1] != 0) any = 1;
        __syncthreads();
        if (threadIdx.x == 0) g_is64 = (any == 0) ? 1 : 0;
    }
}

// grid 4096x256 (1M threads): histogram by dst; first 64K threads also build seg[]
__global__ void k_seghist(const int* __restrict__ ei, const int* __restrict__ batch) {
    int e = blockIdx.x * 256 + threadIdx.x;
    int is64 = g_is64;
    int dst = is64 ? ei[2 * (N_EDGES + e)] : ei[N_EDGES + e];
    atomicAdd(&g_cnt[dst], 1);
    if (e < N_NODES) {
        int i = e;
        int b  = batch[is64 ? 2 * i : i];
        int pb = (i == 0) ? -1 : batch[is64 ? 2 * (i - 1) : (i - 1)];
        for (int g = pb + 1; g <= b; ++g) g_seg[g] = i;
        if (i == N_NODES - 1)
            for (int g = b + 1; g <= N_GRAPHS; ++g) g_seg[g] = N_NODES;
    }
}

// ===================== weight packing =====================
// Wbig rows: [0:64) r: [Wmc_r | Whh_r]; [64:128) z; [128:192) gi_n: [Wmc_n | 0];
// [192:256) gh_n: [0 | Whh_n].   Wmc = Wih[:, :64] @ W_conv  (linearity fold)
__global__ void k_pack(const float* __restrict__ Wmlp, const float* __restrict__ bmlp,
                       const float* __restrict__ gWih, const float* __restrict__ gbih,
                       const float* __restrict__ Wconv, const float* __restrict__ bconv,
                       const float* __restrict__ gWhh,
                       const float* __restrict__ lWih, const float* __restrict__ lWhh,
                       const float* __restrict__ lbih, const float* __restrict__ lbhh) {
    int t0 = blockIdx.x * blockDim.x + threadIdx.x;
    int st = gridDim.x * blockDim.x;
    for (int t = t0; t < 256 * 32; t += st) {
        int o = t >> 5, k = t & 31;
        float v = (o < 64) ? Wmlp[o * 32 + k] : gWih[(o - 64) * 96 + 64 + k];
        float hi = __uint_as_float(f2tf32(v));
        g_W0hi[t] = hi;
        g_W0lo[t] = __uint_as_float(f2tf32(v - hi));
    }
    for (int t = t0; t < 256; t += st)
        g_b0[t] = (t < 64) ? bmlp[t] : gbih[t - 64];
    for (int t = t0; t < 256 * 128; t += st) {
        int o = t >> 7, k = t & 127;
        float v;
        if (k < 64) {
            if (o < 192) {
                float a = 0.f;
#pragma unroll 8
                for (int j = 0; j < 64; j++) a += gWih[o * 96 + j] * Wconv[j * 64 + k];
                v = a;
            } else v = 0.f;
        } else {
            if (o < 128)      v = gWhh[o * 64 + (k - 64)];
            else if (o < 192) v = 0.f;
            else              v = gWhh[(o - 64) * 64 + (k - 64)];
        }
        float hi = __uint_as_float(f2tf32(v));
        g_Wbhi[t] = hi;
        g_Wblo[t] = __uint_as_float(f2tf32(v - hi));
    }
    for (int t = t0; t < 192; t += st) {
        float a = 0.f;
#pragma unroll 8
        for (int j = 0; j < 64; j++) a += gWih[t * 96 + j] * bconv[j];
        g_bmc[t] = a;
    }
    for (int t = t0; t < 256; t += st) g_bzero[t] = 0.f;
    // LSTM weights, k-major: WlT[k][o], k in [0,192) over [q_star | hl]
    for (int t = t0; t < 192 * 256; t += st) {
        int k = t >> 8, o = t & 255;
        g_WlT[t] = (k < 128) ? lWih[o * 128 + k] : lWhh[o * 64 + (k - 128)];
    }
    for (int t = t0; t < 256; t += st) g_bl[t] = lbih[t] + lbhh[t];
}

// ===================== parallel CSR scan =====================
__global__ void k_scanA() {            // grid 256x256: block sums of cnt
    __shared__ int red[256];
    int b = blockIdx.x, t = threadIdx.x;
    red[t] = g_cnt[b * 256 + t];
    __syncthreads();
    for (int off = 128; off > 0; off >>= 1) {
        if (t < off) red[t] += red[t + off];
        __syncthreads();
    }
    if (t == 0) g_bsum[b] = red[0];
}

__global__ void k_scanB() {            // 1 block x256: exclusive scan of block sums
    __shared__ int part[256];
    int t = threadIdx.x;
    int v = g_bsum[t];
    part[t] = v;
    __syncthreads();
    for (int off = 1; off < 256; off <<= 1) {
        int u = (t >= off) ? part[t - off] : 0;
        __syncthreads();
        part[t] += u;
        __syncthreads();
    }
    g_boff[t] = part[t] - v;           // exclusive
}

__global__ void k_scanC() {            // grid 256x256: local scan + offset -> rowptr/cursor
    __shared__ int part[256];
    int b = blockIdx.x, t = threadIdx.x;
    int c = g_cnt[b * 256 + t];
    part[t] = c;
    __syncthreads();
    for (int off = 1; off < 256; off <<= 1) {
        int u = (t >= off) ? part[t - off] : 0;
        __syncthreads();
        part[t] += u;
        __syncthreads();
    }
    int excl = g_boff[b] + part[t] - c;
    g_rowptr[b * 256 + t] = excl;
    g_cursor[b * 256 + t] = excl;
    if (b == 255 && t == 255) g_rowptr[N_NODES] = excl + c;
}

__global__ void k_fill(const int* __restrict__ ei) {
    int e = blockIdx.x * 256 + threadIdx.x;
    int src, dst;
    if (g_is64) { src = ei[2 * e]; dst = ei[2 * (N_EDGES + e)]; }
    else        { src = ei[e];     dst = ei[N_EDGES + e]; }
    int pos = atomicAdd(&g_cursor[dst], 1);
    g_csrc[pos] = src;
}

// m0[n] = sum over in-edges of out[src], order-independent via int64 fixed-point
#define FPSCALE   1099511627776.f      // 2^40
#define FPINV     9.094947017729282e-13f
__global__ void k_gather() {
    unsigned t = blockIdx.x * 256u + threadIdx.x;   // N*16 threads
    int n = t >> 4, c = t & 15;
    int beg = g_rowptr[n], end = g_rowptr[n + 1];
    const float4* o4 = reinterpret_cast<const float4*>(g_out);
    long long ax = 0, ay = 0, az = 0, aw = 0;
#pragma unroll 4
    for (int i = beg; i < end; i++) {
        int s = g_csrc[i];
        float4 v = o4[s * 16 + c];
        ax += __float2ll_rn(v.x * FPSCALE);
        ay += __float2ll_rn(v.y * FPSCALE);
        az += __float2ll_rn(v.z * FPSCALE);
        aw += __float2ll_rn(v.w * FPSCALE);
    }
    float4 acc;
    acc.x = (float)ax * FPINV;
    acc.y = (float)ay * FPINV;
    acc.z = (float)az * FPINV;
    acc.w = (float)aw * FPINV;
    reinterpret_cast<float4*>(g_m0)[n * 16 + c] = acc;
}

// ===================== tensor-core GEMM: mma.sync tf32, 3x split =====================
// C[65536, 256] = concat(A0[:, :aw], A1)[M, NC*32] @ W[256, NC*32]^T + bias
// CTA tile 128x64, 8 warps as 4(m) x 2(n), warp tile 32x32 (2 m16 x 4 n8).
// smem row stride 36 (== 4 mod 32 -> fragment LDS conflict-free).
// NOTE: plain __launch_bounds__(256). Round-15 lesson: forcing minBlocks=4
// (regs 66->64) spilled into the inner loop and DOUBLED kernel time.
template <int NC>
__global__ void __launch_bounds__(256) k_mma(
    const float* __restrict__ A0, const float* __restrict__ A1, int aw,
    const float* __restrict__ Whi, const float* __restrict__ Wlo, int wstride,
    const float* __restrict__ bias,
    float* __restrict__ d1, float* __restrict__ d2, int split, int ld1, int ld2) {
    constexpr int KC = 32, KCp = 36;
    extern __shared__ float sm[];
    float* Ah = sm;                      // [128][36]
    float* Al = Ah + 128 * KCp;
    float* Wh = Al + 128 * KCp;          // [64][36]
    float* Wl = Wh + 64 * KCp;

    const int tid = threadIdx.x;
    const int lane = tid & 31, wid = tid >> 5;
    const int wm = wid >> 1, wn = wid & 1;
    const int r0 = blockIdx.x * 128;
    const int c0 = blockIdx.y * 64;
    const int gq = lane >> 2, tg = lane & 3;

    float acc[2][4][4];
#pragma unroll
    for (int mt = 0; mt < 2; mt++)
#pragma unroll
        for (int nt = 0; nt < 4; nt++)
#pragma unroll
            for (int j = 0; j < 4; j++) acc[mt][nt][j] = 0.f;

    for (int ch = 0; ch < NC; ch++) {
        const int off = ch * KC;
        const float* S;
        int w, soff;
        if (off < aw) { S = A0; w = aw; soff = off; }
        else          { S = A1; w = NC * 32 - aw; soff = off - aw; }
        // stage A chunk, convert fp32 -> tf32 hi/lo
        for (int i4 = tid; i4 < 128 * 8; i4 += 256) {
            int r = i4 >> 3, q = i4 & 7;
            float4 v = *reinterpret_cast<const float4*>(&S[(size_t)(r0 + r) * w + soff + q * 4]);
            float* ph = &Ah[r * KCp + q * 4];
            float* pl = &Al[r * KCp + q * 4];
            float h0 = __uint_as_float(f2tf32(v.x));
            float h1 = __uint_as_float(f2tf32(v.y));
            float h2 = __uint_as_float(f2tf32(v.z));
            float h3 = __uint_as_float(f2tf32(v.w));
            ph[0] = h0; ph[1] = h1; ph[2] = h2; ph[3] = h3;
            pl[0] = __uint_as_float(f2tf32(v.x - h0));
            pl[1] = __uint_as_float(f2tf32(v.y - h1));
            pl[2] = __uint_as_float(f2tf32(v.z - h2));
            pl[3] = __uint_as_float(f2tf32(v.w - h3));
        }
        // stage W chunk (pre-split hi/lo in gmem)
        for (int i4 = tid; i4 < 64 * 8; i4 += 256) {
            int o = i4 >> 3, q = i4 & 7;
            size_t gi = (size_t)(c0 + o) * wstride + off + q * 4;
            float4 vh = *reinterpret_cast<const float4*>(&Whi[gi]);
            float4 vl = *reinterpret_cast<const float4*>(&Wlo[gi]);
            float* ph = &Wh[o * KCp + q * 4];
            float* pl = &Wl[o * KCp + q * 4];
            ph[0] = vh.x; ph[1] = vh.y; ph[2] = vh.z; ph[3] = vh.w;
            pl[0] = vl.x; pl[1] = vl.y; pl[2] = vl.z; pl[3] = vl.w;
        }
        __syncthreads();

#pragma unroll
        for (int kk = 0; kk < KC; kk += 8) {
            uint32_t ah[2][4], al[2][4], bh[4][2], bl[4][2];
#pragma unroll
            for (int mt = 0; mt < 2; mt++) {
                int rb = wm * 32 + mt * 16 + gq;
                const float* pa = &Ah[rb * KCp + kk + tg];
                const float* pl = &Al[rb * KCp + kk + tg];
                ah[mt][0] = __float_as_uint(pa[0]);
                ah[mt][1] = __float_as_uint(pa[8 * KCp]);
                ah[mt][2] = __float_as_uint(pa[4]);
                ah[mt][3] = __float_as_uint(pa[8 * KCp + 4]);
                al[mt][0] = __float_as_uint(pl[0]);
                al[mt][1] = __float_as_uint(pl[8 * KCp]);
                al[mt][2] = __float_as_uint(pl[4]);
                al[mt][3] = __float_as_uint(pl[8 * KCp + 4]);
            }
#pragma unroll
            for (int nt = 0; nt < 4; nt++) {
                int cb = wn * 32 + nt * 8 + gq;
                const float* pb = &Wh[cb * KCp + kk + tg];
                const float* pq = &Wl[cb * KCp + kk + tg];
                bh[nt][0] = __float_as_uint(pb[0]);
                bh[nt][1] = __float_as_uint(pb[4]);
                bl[nt][0] = __float_as_uint(pq[0]);
                bl[nt][1] = __float_as_uint(pq[4]);
            }
#pragma unroll
            for (int mt = 0; mt < 2; mt++)
#pragma unroll
                for (int nt = 0; nt < 4; nt++) {
                    MMA_TF32(acc[mt][nt], ah[mt], bh[nt]);
                    MMA_TF32(acc[mt][nt], al[mt], bh[nt]);
                    MMA_TF32(acc[mt][nt], ah[mt], bl[nt]);
                }
        }
        __syncthreads();
    }

    // epilogue: c0=(g,2tg) c1=(g,2tg+1) c2=(g+8,2tg) c3=(g+8,2tg+1)
#pragma unroll
    for (int mt = 0; mt < 2; mt++) {
        int row0 = r0 + wm * 32 + mt * 16 + gq;
#pragma unroll
        for (int nt = 0; nt < 4; nt++) {
            int col = c0 + wn * 32 + nt * 8 + 2 * tg;
            float b0v = bias[col], b1v = bias[col + 1];
            float2 v0 = make_float2(acc[mt][nt][0] + b0v, acc[mt][nt][1] + b1v);
            float2 v1 = make_float2(acc[mt][nt][2] + b0v, acc[mt][nt][3] + b1v);
            if (col < split) {
                *reinterpret_cast<float2*>(&d1[(size_t)row0 * ld1 + col]) = v0;
                *reinterpret_cast<float2*>(&d1[(size_t)(row0 + 8) * ld1 + col]) = v1;
            } else {
                *reinterpret_cast<float2*>(&d2[(size_t)row0 * ld2 + (col - split)]) = v0;
                *reinterpret_cast<float2*>(&d2[(size_t)(row0 + 8) * ld2 + (col - split)]) = v1;
            }
        }
    }
}

// ===================== GRU elementwise =====================
__global__ void k_gru(const float* __restrict__ bhh) {
    int t = blockIdx.x * 256 + threadIdx.x;     // N*64 threads
    int n = t >> 6, j = t & 63;
    float deg = (float)(g_rowptr[n + 1] - g_rowptr[n]);
    const float* gg = g_gg + (size_t)n * 256;
    const float* gx = g_gx + (size_t)n * 192;
    float rpre = gg[j]       + gx[j]       + deg * g_bmc[j]       + bhh[j];
    float zpre = gg[64 + j]  + gx[64 + j]  + deg * g_bmc[64 + j]  + bhh[64 + j];
    float ginn = gg[128 + j] + gx[128 + j] + deg * g_bmc[128 + j];
    float ghnn = gg[192 + j] + bhh[128 + j];
    float r = 1.f / (1.f + expf(-rpre));
    float z = 1.f / (1.f + expf(-zpre));
    float ng = tanhf(ginn + r * ghnn);
    g_out[t] = (1.f - z) * ng + z * g_out[t];
}

// ===================== fused Set2Set iteration =====================
// block per graph: LSTM gates (k-major W, coalesced) + combine + segmented
// softmax attention + q_star write. first=1 treats q_star/hl/cl as zero.
__global__ void __launch_bounds__(256) k_s2s(const float* __restrict__ WlT,
                                             const float* __restrict__ bl, int first) {
    int g = blockIdx.x;
    int tid = threadIdx.x, lane = tid & 31, warp = tid >> 5;
    __shared__ float sq[192];
    __shared__ float sg[256];
    __shared__ float sh[64];
    __shared__ float sred[8];
    __shared__ float rsm[8][64];

    if (tid < 192)
        sq[tid] = first ? 0.f
                        : (tid < 128 ? g_qs[g * 128 + tid] : g_hl[g * 64 + (tid - 128)]);
    __syncthreads();

    // LSTM gates: thread tid computes gate 'tid' over K=192 (coalesced WlT rows)
    float acc = bl[tid];
#pragma unroll 16
    for (int k = 0; k < 192; k++) acc += sq[k] * WlT[k * 256 + tid];
    sg[tid] = acc;
    __syncthreads();

    // combine (PyTorch gate order i,f,g,o)
    if (tid < 64) {
        float gi = sg[tid], gf = sg[64 + tid], gg = sg[128 + tid], go = sg[192 + tid];
        float cp = first ? 0.f : g_cl[g * 64 + tid];
        float c = 1.f / (1.f + expf(-gf)) * cp + 1.f / (1.f + expf(-gi)) * tanhf(gg);
        g_cl[g * 64 + tid] = c;
        float h = 1.f / (1.f + expf(-go)) * tanhf(c);
        g_hl[g * 64 + tid] = h;
        sh[tid] = h;
    }
    __syncthreads();

    // segmented softmax attention with q = sh
    int n0 = g_seg[g], n1 = g_seg[g + 1];
    float q0 = sh[lane], q1 = sh[lane + 32];
    float wmax = -3.402823466e38f;
    for (int i = n0 + warp; i < n1; i += 8) {
        float p = g_out[i * 64 + lane] * q0 + g_out[i * 64 + 32 + lane] * q1;
#pragma unroll
        for (int s = 16; s > 0; s >>= 1) p += __shfl_xor_sync(0xffffffffu, p, s);
        if (lane == 0) g_e[i] = p;
        wmax = fmaxf(wmax, p);
    }
    if (lane == 0) sred[warp] = wmax;
    __syncthreads();
    if (tid == 0) {
        float m2 = -3.402823466e38f;
        for (int w = 0; w < 8; w++) m2 = fmaxf(m2, sred[w]);
        sred[0] = m2;
    }
    __syncthreads();
    float emax = sred[0];
    __syncthreads();
    float s = 0.f;
    for (int i = n0 + tid; i < n1; i += 256) {
        float v = expf(g_e[i] - emax);
        g_e[i] = v;
        s += v;
    }
#pragma unroll
    for (int sh2 = 16; sh2 > 0; sh2 >>= 1) s += __shfl_xor_sync(0xffffffffu, s, sh2);
    if (lane == 0) sred[warp] = s;
    __syncthreads();
    if (tid == 0) {
        float t2 = 0.f;
        for (int w = 0; w < 8; w++) t2 += sred[w];
        sred[0] = t2;
    }
    __syncthreads();
    float asum = sred[0];
    float r0 = 0.f, r1 = 0.f;
    for (int i = n0 + warp; i < n1; i += 8) {
        float a = g_e[i];
        r0 += a * g_out[i * 64 + lane];
        r1 += a * g_out[i * 64 + 32 + lane];
    }
    rsm[warp][lane] = r0;
    rsm[warp][lane + 32] = r1;
    __syncthreads();
    float inv = 1.f / fmaxf(asum, 1e-16f);
    if (tid < 64) {
        float a2 = 0.f;
        for (int w = 0; w < 8; w++) a2 += rsm[w][tid];
        g_qs[g * 128 + 64 + tid] = a2 * inv;
    } else if (tid < 128) {
        g_qs[g * 128 + (tid - 64)] = sh[tid - 64];
    }
}

// ===================== head =====================
__global__ void __launch_bounds__(128) k_head(const float* __restrict__ W1,
                                              const float* __restrict__ b1,
                                              const float* __restrict__ W2,
                                              const float* __restrict__ b2,
                                              float* __restrict__ outp) {
    __shared__ float sW1[64 * 128];
    __shared__ float sW2[4 * 64];
    __shared__ float sq[128];
    __shared__ float hid[64];
    __shared__ float lg[4];
    int g = blockIdx.x, tid = threadIdx.x;
    for (int i = tid; i < 64 * 128; i += 128) sW1[i] = W1[i];
    for (int i = tid; i < 256; i += 128) sW2[i] = W2[i];
    sq[tid] = g_qs[g * 128 + tid];
    __syncthreads();
    if (tid < 64) {
        float acc = b1[tid];
#pragma unroll 8
        for (int k = 0; k < 128; k++) acc += sq[k] * sW1[tid * 128 + k];
        hid[tid] = fmaxf(acc, 0.f);
    }
    __syncthreads();
    if (tid < 4) {
        float acc = b2[tid];
#pragma unroll
        for (int k = 0; k < 64; k++) acc += hid[k] * sW2[tid * 64 + k];
        lg[tid] = acc;
    }
    __syncthreads();
    if (tid == 0) {
        float m = fmaxf(fmaxf(lg[0], lg[1]), fmaxf(lg[2], lg[3]));
        float sum = expf(lg[0] - m) + expf(lg[1] - m) + expf(lg[2] - m) + expf(lg[3] - m);
        float l = m + logf(sum);
        outp[g * 4 + 0] = lg[0] - l;
        outp[g * 4 + 1] = lg[1] - l;
        outp[g * 4 + 2] = lg[2] - l;
        outp[g * 4 + 3] = lg[3] - l;
    }
}

// ===================== launcher =====================
extern "C" void kernel_launch(void* const* d_in, const int* in_sizes, int n_in,
                              void* d_out, int out_size) {
    const float* x      = (const float*)d_in[0];
    const int*   ei     = (const int*)d_in[1];
    const int*   batch  = (const int*)d_in[2];
    const float* W_mlp  = (const float*)d_in[3];
    const float* b_mlp  = (const float*)d_in[4];
    const float* W_conv = (const float*)d_in[5];
    const float* b_conv = (const float*)d_in[6];
    const float* gWih   = (const float*)d_in[7];
    const float* gWhh   = (const float*)d_in[8];
    const float* gbih   = (const float*)d_in[9];
    const float* gbhh   = (const float*)d_in[10];
    const float* lWih   = (const float*)d_in[11];
    const float* lWhh   = (const float*)d_in[12];
    const float* lbih   = (const float*)d_in[13];
    const float* lbhh   = (const float*)d_in[14];
    const float* W1     = (const float*)d_in[15];
    const float* b1     = (const float*)d_in[16];
    const float* W2     = (const float*)d_in[17];
    const float* b2     = (const float*)d_in[18];

    float *p_out, *p_gx, *p_m0, *p_gg;
    float *p_W0hi, *p_W0lo, *p_b0, *p_Wbhi, *p_Wblo, *p_bzero, *p_WlT, *p_bl;
    cudaGetSymbolAddress((void**)&p_out, g_out);
    cudaGetSymbolAddress((void**)&p_gx, g_gx);
    cudaGetSymbolAddress((void**)&p_m0, g_m0);
    cudaGetSymbolAddress((void**)&p_gg, g_gg);
    cudaGetSymbolAddress((void**)&p_W0hi, g_W0hi);
    cudaGetSymbolAddress((void**)&p_W0lo, g_W0lo);
    cudaGetSymbolAddress((void**)&p_b0, g_b0);
    cudaGetSymbolAddress((void**)&p_Wbhi, g_Wbhi);
    cudaGetSymbolAddress((void**)&p_Wblo, g_Wblo);
    cudaGetSymbolAddress((void**)&p_bzero, g_bzero);
    cudaGetSymbolAddress((void**)&p_WlT, g_WlT);
    cudaGetSymbolAddress((void**)&p_bl, g_bl);

    const int MMA_SMEM = (128 + 128 + 64 + 64) * 36 * 4;   // 55296 B
    cudaFuncSetAttribute((const void*)k_mma<1>, cudaFuncAttributeMaxDynamicSharedMemorySize, MMA_SMEM);
    cudaFuncSetAttribute((const void*)k_mma<4>, cudaFuncAttributeMaxDynamicSharedMemorySize, MMA_SMEM);

    // static side stream + events for graph-captured fork/join
    static cudaStream_t s1 = nullptr;
    static cudaEvent_t ev_fork = nullptr, ev_join = nullptr;
    if (!s1) {
        cudaStreamCreateWithFlags(&s1, cudaStreamNonBlocking);
        cudaEventCreateWithFlags(&ev_fork, cudaEventDisableTiming);
        cudaEventCreateWithFlags(&ev_join, cudaEventDisableTiming);
    }

    // host-launch order arranged so k_mma<1> is index 3 (ncu capture window).
    k_detect<<<256, 256>>>(ei);                          // 0
    cudaEventRecord(ev_fork, 0);
    cudaStreamWaitEvent(s1, ev_fork, 0);

    k_seghist<<<N_EDGES / 256, 256, 0, s1>>>(ei, batch); // 1 (side)
    k_pack<<<128, 256>>>(W_mlp, b_mlp, gWih, gbih, W_conv, b_conv, gWhh,
                         lWih, lWhh, lbih, lbhh);        // 2 (main)
    // [out | gx] = x @ [W_mlp ; Wx]^T + [b_mlp ; b_ih]
    k_mma<1><<<dim3(512, 4), 256, MMA_SMEM>>>(x, x, 32, p_W0hi, p_W0lo, 32, p_b0,
                                              p_out, p_gx, 64, 64, 192);  // 3

    // rest of side-stream CSR chain
    k_scanA<<<256, 256, 0, s1>>>();
    k_scanB<<<1, 256, 0, s1>>>();
    k_scanC<<<256, 256, 0, s1>>>();
    k_fill<<<N_EDGES / 256, 256, 0, s1>>>(ei);
    cudaEventRecord(ev_join, s1);

    // join: gather needs CSR (side) + out (main)
    cudaStreamWaitEvent(0, ev_join, 0);

    for (int s = 0; s < 2; s++) {
        k_gather<<<N_NODES * 16 / 256, 256>>>();
        k_mma<4><<<dim3(512, 4), 256, MMA_SMEM>>>(p_m0, p_out, 64, p_Wbhi, p_Wblo, 128,
                                                  p_bzero, p_gg, p_gg, 256, 256, 256);
        k_gru<<<N_NODES * 64 / 256, 256>>>(gbhh);
    }

    // fused Set2Set: 3 launches, no zero-init kernels (first flag)
    k_s2s<<<256, 256>>>(p_WlT, p_bl, 1);
    k_s2s<<<256, 256>>>(p_WlT, p_bl, 0);
    k_s2s<<<256, 256>>>(p_WlT, p_bl, 0);

    k_head<<<256, 128>>>(W1, b1, W2, b2, (float*)d_out);
}

// round 17
// speedup vs baseline: 1.5741x; 1.0988x over previous
#include <cuda_runtime.h>
#include <cstdint>
#include <math.h>

#define N_NODES 65536
#define N_EDGES 1048576
#define N_GRAPHS 256

// ===================== device scratch =====================
__device__ __align__(16) float g_out[N_NODES * 64];        // node state h/out
__device__ __align__(16) float g_gx[N_NODES * 192];        // x @ Wx^T + b_ih (loop invariant)
__device__ __align__(16) float g_m0[N_NODES * 64];         // gather-sum of out[src]
__device__ __align__(16) float g_gg[N_NODES * 256];        // fused GEMM out (r,z,gi_n,gh_n)
__device__ __align__(16) float g_e[N_NODES];               // attention logits / weights

__device__ __align__(16) float g_W0hi[256 * 32];           // [W_mlp ; Wx] tf32-hi
__device__ __align__(16) float g_W0lo[256 * 32];
__device__ __align__(16) float g_b0[256];
__device__ __align__(16) float g_Wbhi[256 * 128];          // fused step weights tf32-hi
__device__ __align__(16) float g_Wblo[256 * 128];
__device__ __align__(16) float g_bmc[192];                 // Wm @ b_conv
__device__ __align__(16) float g_bzero[256];
__device__ __align__(16) float g_WlT[192 * 256];           // LSTM [W_ih|W_hh] k-major
__device__ __align__(16) float g_bl[256];

__device__ __align__(16) float g_qs[N_GRAPHS * 128];
__device__ __align__(16) float g_hl[N_GRAPHS * 64];
__device__ __align__(16) float g_cl[N_GRAPHS * 64];

__device__ __align__(16) int g_cnt[N_NODES];
__device__ __align__(16) int g_rowptr[N_NODES + 1];
__device__ __align__(16) int g_cursor[N_NODES];
__device__ __align__(16) int g_csrc[N_EDGES];
__device__ __align__(16) int g_bsum[256];
__device__ __align__(16) int g_boff[256];

__device__ int g_seg[N_GRAPHS + 1];
__device__ int g_is64;

// ===================== helpers =====================
__device__ __forceinline__ uint32_t f2tf32(float x) {
    uint32_t r;
    asm("cvt.rna.tf32.f32 %0, %1;" : "=r"(r) : "f"(x));
    return r;
}

// m16n8k8 tf32 warp mma, D += A*B (arch-neutral PTX, works on compute_103 base)
#define MMA_TF32(c, a, b) \
    asm volatile("mma.sync.aligned.m16n8k8.row.col.f32.tf32.tf32.f32 " \
        "{%0,%1,%2,%3}, {%4,%5,%6,%7}, {%8,%9}, {%0,%1,%2,%3};" \
        : "+f"((c)[0]), "+f"((c)[1]), "+f"((c)[2]), "+f"((c)[3]) \
        : "r"((a)[0]), "r"((a)[1]), "r"((a)[2]), "r"((a)[3]), \
          "r"((b)[0]), "r"((b)[1]))

// ===================== setup kernels =====================
// grid 256x256: zero g_cnt (65536 ints); block 0 additionally detects int64 indices
__global__ void k_detect(const int* __restrict__ ei) {
    int t = blockIdx.x * 256 + threadIdx.x;
    g_cnt[t] = 0;
    if (blockIdx.x == 0) {
        __shared__ int any;
        if (threadIdx.x == 0) any = 0;
        __syncthreads();
        for (int i = threadIdx.x; i < 2048; i += 256)
            if (ei[2 * i + 1] != 0) any = 1;
        __syncthreads();
        if (threadIdx.x == 0) g_is64 = (any == 0) ? 1 : 0;
    }
}

// grid 4096x256 (1M threads): histogram by dst; first 64K threads also build seg[]
__global__ void k_seghist(const int* __restrict__ ei, const int* __restrict__ batch) {
    int e = blockIdx.x * 256 + threadIdx.x;
    int is64 = g_is64;
    int dst = is64 ? ei[2 * (N_EDGES + e)] : ei[N_EDGES + e];
    atomicAdd(&g_cnt[dst], 1);
    if (e < N_NODES) {
        int i = e;
        int b  = batch[is64 ? 2 * i : i];
        int pb = (i == 0) ? -1 : batch[is64 ? 2 * (i - 1) : (i - 1)];
        for (int g = pb + 1; g <= b; ++g) g_seg[g] = i;
        if (i == N_NODES - 1)
            for (int g = b + 1; g <= N_GRAPHS; ++g) g_seg[g] = N_NODES;
    }
}

// ===================== weight packing =====================
// Wbig rows: [0:64) r: [Wmc_r | Whh_r]; [64:128) z; [128:192) gi_n: [Wmc_n | 0];
// [192:256) gh_n: [0 | Whh_n].   Wmc = Wih[:, :64] @ W_conv  (linearity fold)
__global__ void k_pack(const float* __restrict__ Wmlp, const float* __restrict__ bmlp,
                       const float* __restrict__ gWih, const float* __restrict__ gbih,
                       const float* __restrict__ Wconv, const float* __restrict__ bconv,
                       const float* __restrict__ gWhh,
                       const float* __restrict__ lWih, const float* __restrict__ lWhh,
                       const float* __restrict__ lbih, const float* __restrict__ lbhh) {
    int t0 = blockIdx.x * blockDim.x + threadIdx.x;
    int st = gridDim.x * blockDim.x;
    for (int t = t0; t < 256 * 32; t += st) {
        int o = t >> 5, k = t & 31;
        float v = (o < 64) ? Wmlp[o * 32 + k] : gWih[(o - 64) * 96 + 64 + k];
        float hi = __uint_as_float(f2tf32(v));
        g_W0hi[t] = hi;
        g_W0lo[t] = __uint_as_float(f2tf32(v - hi));
    }
    for (int t = t0; t < 256; t += st)
        g_b0[t] = (t < 64) ? bmlp[t] : gbih[t - 64];
    for (int t = t0; t < 256 * 128; t += st) {
        int o = t >> 7, k = t & 127;
        float v;
        if (k < 64) {
            if (o < 192) {
                float a = 0.f;
#pragma unroll 8
                for (int j = 0; j < 64; j++) a += gWih[o * 96 + j] * Wconv[j * 64 + k];
                v = a;
            } else v = 0.f;
        } else {
            if (o < 128)      v = gWhh[o * 64 + (k - 64)];
            else if (o < 192) v = 0.f;
            else              v = gWhh[(o - 64) * 64 + (k - 64)];
        }
        float hi = __uint_as_float(f2tf32(v));
        g_Wbhi[t] = hi;
        g_Wblo[t] = __uint_as_float(f2tf32(v - hi));
    }
    for (int t = t0; t < 192; t += st) {
        float a = 0.f;
#pragma unroll 8
        for (int j = 0; j < 64; j++) a += gWih[t * 96 + j] * bconv[j];
        g_bmc[t] = a;
    }
    for (int t = t0; t < 256; t += st) g_bzero[t] = 0.f;
    // LSTM weights, k-major: WlT[k][o], k in [0,192) over [q_star | hl]
    for (int t = t0; t < 192 * 256; t += st) {
        int k = t >> 8, o = t & 255;
        g_WlT[t] = (k < 128) ? lWih[o * 128 + k] : lWhh[o * 64 + (k - 128)];
    }
    for (int t = t0; t < 256; t += st) g_bl[t] = lbih[t] + lbhh[t];
}

// ===================== parallel CSR scan =====================
__global__ void k_scanA() {            // grid 256x256: block sums of cnt
    __shared__ int red[256];
    int b = blockIdx.x, t = threadIdx.x;
    red[t] = g_cnt[b * 256 + t];
    __syncthreads();
    for (int off = 128; off > 0; off >>= 1) {
        if (t < off) red[t] += red[t + off];
        __syncthreads();
    }
    if (t == 0) g_bsum[b] = red[0];
}

__global__ void k_scanB() {            // 1 block x256: exclusive scan of block sums
    __shared__ int part[256];
    int t = threadIdx.x;
    int v = g_bsum[t];
    part[t] = v;
    __syncthreads();
    for (int off = 1; off < 256; off <<= 1) {
        int u = (t >= off) ? part[t - off] : 0;
        __syncthreads();
        part[t] += u;
        __syncthreads();
    }
    g_boff[t] = part[t] - v;           // exclusive
}

__global__ void k_scanC() {            // grid 256x256: local scan + offset -> rowptr/cursor
    __shared__ int part[256];
    int b = blockIdx.x, t = threadIdx.x;
    int c = g_cnt[b * 256 + t];
    part[t] = c;
    __syncthreads();
    for (int off = 1; off < 256; off <<= 1) {
        int u = (t >= off) ? part[t - off] : 0;
        __syncthreads();
        part[t] += u;
        __syncthreads();
    }
    int excl = g_boff[b] + part[t] - c;
    g_rowptr[b * 256 + t] = excl;
    g_cursor[b * 256 + t] = excl;
    if (b == 255 && t == 255) g_rowptr[N_NODES] = excl + c;
}

__global__ void k_fill(const int* __restrict__ ei) {
    int e = blockIdx.x * 256 + threadIdx.x;
    int src, dst;
    if (g_is64) { src = ei[2 * e]; dst = ei[2 * (N_EDGES + e)]; }
    else        { src = ei[e];     dst = ei[N_EDGES + e]; }
    int pos = atomicAdd(&g_cursor[dst], 1);
    g_csrc[pos] = src;
}

// m0[n] = sum over in-edges of out[src], order-independent via int64 fixed-point
#define FPSCALE   1099511627776.f      // 2^40
#define FPINV     9.094947017729282e-13f
__global__ void k_gather() {
    unsigned t = blockIdx.x * 256u + threadIdx.x;   // N*16 threads
    int n = t >> 4, c = t & 15;
    int beg = g_rowptr[n], end = g_rowptr[n + 1];
    const float4* o4 = reinterpret_cast<const float4*>(g_out);
    long long ax = 0, ay = 0, az = 0, aw = 0;
#pragma unroll 4
    for (int i = beg; i < end; i++) {
        int s = g_csrc[i];
        float4 v = o4[s * 16 + c];
        ax += __float2ll_rn(v.x * FPSCALE);
        ay += __float2ll_rn(v.y * FPSCALE);
        az += __float2ll_rn(v.z * FPSCALE);
        aw += __float2ll_rn(v.w * FPSCALE);
    }
    float4 acc;
    acc.x = (float)ax * FPINV;
    acc.y = (float)ay * FPINV;
    acc.z = (float)az * FPINV;
    acc.w = (float)aw * FPINV;
    reinterpret_cast<float4*>(g_m0)[n * 16 + c] = acc;
}

// ===================== tensor-core GEMM: mma.sync tf32, 3x split =====================
// C[65536, 256] = concat(A0[:, :aw], A1)[M, NC*32] @ W[256, NC*32]^T + bias
// CTA tile 128x64, 8 warps as 4(m) x 2(n), warp tile 32x32 (2 m16 x 4 n8).
// smem row stride 36 (== 4 mod 32 -> fragment LDS conflict-free).
// zskip=1 (step GEMM): W col-tile y=2 (gi_n rows) is zero in K[64:128) and
// y=3 (gh_n rows) is zero in K[0:64) -> skip those chunks. Numerically exact
// (register accumulator starts at 0; skipped products are exactly 0).
// NOTE: plain __launch_bounds__(256). Round-15 lesson: forcing minBlocks=4
// (regs 66->64) spilled into the inner loop and DOUBLED kernel time.
template <int NC>
__global__ void __launch_bounds__(256) k_mma(
    const float* __restrict__ A0, const float* __restrict__ A1, int aw,
    const float* __restrict__ Whi, const float* __restrict__ Wlo, int wstride,
    const float* __restrict__ bias,
    float* __restrict__ d1, float* __restrict__ d2, int split, int ld1, int ld2,
    int zskip) {
    constexpr int KC = 32, KCp = 36;
    extern __shared__ float sm[];
    float* Ah = sm;                      // [128][36]
    float* Al = Ah + 128 * KCp;
    float* Wh = Al + 128 * KCp;          // [64][36]
    float* Wl = Wh + 64 * KCp;

    const int tid = threadIdx.x;
    const int lane = tid & 31, wid = tid >> 5;
    const int wm = wid >> 1, wn = wid & 1;
    const int r0 = blockIdx.x * 128;
    const int c0 = blockIdx.y * 64;
    const int gq = lane >> 2, tg = lane & 3;

    int ch_beg = 0, ch_end = NC;
    if (zskip) {
        if (blockIdx.y == 2) ch_end = NC / 2;        // gi_n: only K[0:64) (m0) nonzero
        else if (blockIdx.y == 3) ch_beg = NC / 2;   // gh_n: only K[64:128) (out) nonzero
    }

    float acc[2][4][4];
#pragma unroll
    for (int mt = 0; mt < 2; mt++)
#pragma unroll
        for (int nt = 0; nt < 4; nt++)
#pragma unroll
            for (int j = 0; j < 4; j++) acc[mt][nt][j] = 0.f;

    for (int ch = ch_beg; ch < ch_end; ch++) {
        const int off = ch * KC;
        const float* S;
        int w, soff;
        if (off < aw) { S = A0; w = aw; soff = off; }
        else          { S = A1; w = NC * 32 - aw; soff = off - aw; }
        // stage A chunk, convert fp32 -> tf32 hi/lo
        for (int i4 = tid; i4 < 128 * 8; i4 += 256) {
            int r = i4 >> 3, q = i4 & 7;
            float4 v = *reinterpret_cast<const float4*>(&S[(size_t)(r0 + r) * w + soff + q * 4]);
            float* ph = &Ah[r * KCp + q * 4];
            float* pl = &Al[r * KCp + q * 4];
            float h0 = __uint_as_float(f2tf32(v.x));
            float h1 = __uint_as_float(f2tf32(v.y));
            float h2 = __uint_as_float(f2tf32(v.z));
            float h3 = __uint_as_float(f2tf32(v.w));
            ph[0] = h0; ph[1] = h1; ph[2] = h2; ph[3] = h3;
            pl[0] = __uint_as_float(f2tf32(v.x - h0));
            pl[1] = __uint_as_float(f2tf32(v.y - h1));
            pl[2] = __uint_as_float(f2tf32(v.z - h2));
            pl[3] = __uint_as_float(f2tf32(v.w - h3));
        }
        // stage W chunk (pre-split hi/lo in gmem)
        for (int i4 = tid; i4 < 64 * 8; i4 += 256) {
            int o = i4 >> 3, q = i4 & 7;
            size_t gi = (size_t)(c0 + o) * wstride + off + q * 4;
            float4 vh = *reinterpret_cast<const float4*>(&Whi[gi]);
            float4 vl = *reinterpret_cast<const float4*>(&Wlo[gi]);
            float* ph = &Wh[o * KCp + q * 4];
            float* pl = &Wl[o * KCp + q * 4];
            ph[0] = vh.x; ph[1] = vh.y; ph[2] = vh.z; ph[3] = vh.w;
            pl[0] = vl.x; pl[1] = vl.y; pl[2] = vl.z; pl[3] = vl.w;
        }
        __syncthreads();

#pragma unroll
        for (int kk = 0; kk < KC; kk += 8) {
            uint32_t ah[2][4], al[2][4], bh[4][2], bl[4][2];
#pragma unroll
            for (int mt = 0; mt < 2; mt++) {
                int rb = wm * 32 + mt * 16 + gq;
                const float* pa = &Ah[rb * KCp + kk + tg];
                const float* pl = &Al[rb * KCp + kk + tg];
                ah[mt][0] = __float_as_uint(pa[0]);
                ah[mt][1] = __float_as_uint(pa[8 * KCp]);
                ah[mt][2] = __float_as_uint(pa[4]);
                ah[mt][3] = __float_as_uint(pa[8 * KCp + 4]);
                al[mt][0] = __float_as_uint(pl[0]);
                al[mt][1] = __float_as_uint(pl[8 * KCp]);
                al[mt][2] = __float_as_uint(pl[4]);
                al[mt][3] = __float_as_uint(pl[8 * KCp + 4]);
            }
#pragma unroll
            for (int nt = 0; nt < 4; nt++) {
                int cb = wn * 32 + nt * 8 + gq;
                const float* pb = &Wh[cb * KCp + kk + tg];
                const float* pq = &Wl[cb * KCp + kk + tg];
                bh[nt][0] = __float_as_uint(pb[0]);
                bh[nt][1] = __float_as_uint(pb[4]);
                bl[nt][0] = __float_as_uint(pq[0]);
                bl[nt][1] = __float_as_uint(pq[4]);
            }
#pragma unroll
            for (int mt = 0; mt < 2; mt++)
#pragma unroll
                for (int nt = 0; nt < 4; nt++) {
                    MMA_TF32(acc[mt][nt], ah[mt], bh[nt]);
                    MMA_TF32(acc[mt][nt], al[mt], bh[nt]);
                    MMA_TF32(acc[mt][nt], ah[mt], bl[nt]);
                }
        }
        __syncthreads();
    }

    // epilogue: c0=(g,2tg) c1=(g,2tg+1) c2=(g+8,2tg) c3=(g+8,2tg+1)
#pragma unroll
    for (int mt = 0; mt < 2; mt++) {
        int row0 = r0 + wm * 32 + mt * 16 + gq;
#pragma unroll
        for (int nt = 0; nt < 4; nt++) {
            int col = c0 + wn * 32 + nt * 8 + 2 * tg;
            float b0v = bias[col], b1v = bias[col + 1];
            float2 v0 = make_float2(acc[mt][nt][0] + b0v, acc[mt][nt][1] + b1v);
            float2 v1 = make_float2(acc[mt][nt][2] + b0v, acc[mt][nt][3] + b1v);
            if (col < split) {
                *reinterpret_cast<float2*>(&d1[(size_t)row0 * ld1 + col]) = v0;
                *reinterpret_cast<float2*>(&d1[(size_t)(row0 + 8) * ld1 + col]) = v1;
            } else {
                *reinterpret_cast<float2*>(&d2[(size_t)row0 * ld2 + (col - split)]) = v0;
                *reinterpret_cast<float2*>(&d2[(size_t)(row0 + 8) * ld2 + (col - split)]) = v1;
            }
        }
    }
}

// ===================== GRU elementwise =====================
__global__ void k_gru(const float* __restrict__ bhh) {
    int t = blockIdx.x * 256 + threadIdx.x;     // N*64 threads
    int n = t >> 6, j = t & 63;
    float deg = (float)(g_rowptr[n + 1] - g_rowptr[n]);
    const float* gg = g_gg + (size_t)n * 256;
    const float* gx = g_gx + (size_t)n * 192;
    float rpre = gg[j]       + gx[j]       + deg * g_bmc[j]       + bhh[j];
    float zpre = gg[64 + j]  + gx[64 + j]  + deg * g_bmc[64 + j]  + bhh[64 + j];
    float ginn = gg[128 + j] + gx[128 + j] + deg * g_bmc[128 + j];
    float ghnn = gg[192 + j] + bhh[128 + j];
    float r = 1.f / (1.f + expf(-rpre));
    float z = 1.f / (1.f + expf(-zpre));
    float ng = tanhf(ginn + r * ghnn);
    g_out[t] = (1.f - z) * ng + z * g_out[t];
}

// ===================== fused Set2Set iteration =====================
// block per graph: LSTM gates (k-major W, coalesced) + combine + segmented
// softmax attention + q_star write. first=1 treats q_star/hl/cl as zero.
__global__ void __launch_bounds__(256) k_s2s(const float* __restrict__ WlT,
                                             const float* __restrict__ bl, int first) {
    int g = blockIdx.x;
    int tid = threadIdx.x, lane = tid & 31, warp = tid >> 5;
    __shared__ float sq[192];
    __shared__ float sg[256];
    __shared__ float sh[64];
    __shared__ float sred[8];
    __shared__ float rsm[8][64];

    if (tid < 192)
        sq[tid] = first ? 0.f
                        : (tid < 128 ? g_qs[g * 128 + tid] : g_hl[g * 64 + (tid - 128)]);
    __syncthreads();

    // LSTM gates: thread tid computes gate 'tid' over K=192 (coalesced WlT rows)
    float acc = bl[tid];
#pragma unroll 16
    for (int k = 0; k < 192; k++) acc += sq[k] * WlT[k * 256 + tid];
    sg[tid] = acc;
    __syncthreads();

    // combine (PyTorch gate order i,f,g,o)
    if (tid < 64) {
        float gi = sg[tid], gf = sg[64 + tid], gg = sg[128 + tid], go = sg[192 + tid];
        float cp = first ? 0.f : g_cl[g * 64 + tid];
        float c = 1.f / (1.f + expf(-gf)) * cp + 1.f / (1.f + expf(-gi)) * tanhf(gg);
        g_cl[g * 64 + tid] = c;
        float h = 1.f / (1.f + expf(-go)) * tanhf(c);
        g_hl[g * 64 + tid] = h;
        sh[tid] = h;
    }
    __syncthreads();

    // segmented softmax attention with q = sh
    int n0 = g_seg[g], n1 = g_seg[g + 1];
    float q0 = sh[lane], q1 = sh[lane + 32];
    float wmax = -3.402823466e38f;
    for (int i = n0 + warp; i < n1; i += 8) {
        float p = g_out[i * 64 + lane] * q0 + g_out[i * 64 + 32 + lane] * q1;
#pragma unroll
        for (int s = 16; s > 0; s >>= 1) p += __shfl_xor_sync(0xffffffffu, p, s);
        if (lane == 0) g_e[i] = p;
        wmax = fmaxf(wmax, p);
    }
    if (lane == 0) sred[warp] = wmax;
    __syncthreads();
    if (tid == 0) {
        float m2 = -3.402823466e38f;
        for (int w = 0; w < 8; w++) m2 = fmaxf(m2, sred[w]);
        sred[0] = m2;
    }
    __syncthreads();
    float emax = sred[0];
    __syncthreads();
    float s = 0.f;
    for (int i = n0 + tid; i < n1; i += 256) {
        float v = expf(g_e[i] - emax);
        g_e[i] = v;
        s += v;
    }
#pragma unroll
    for (int sh2 = 16; sh2 > 0; sh2 >>= 1) s += __shfl_xor_sync(0xffffffffu, s, sh2);
    if (lane == 0) sred[warp] = s;
    __syncthreads();
    if (tid == 0) {
        float t2 = 0.f;
        for (int w = 0; w < 8; w++) t2 += sred[w];
        sred[0] = t2;
    }
    __syncthreads();
    float asum = sred[0];
    float r0 = 0.f, r1 = 0.f;
    for (int i = n0 + warp; i < n1; i += 8) {
        float a = g_e[i];
        r0 += a * g_out[i * 64 + lane];
        r1 += a * g_out[i * 64 + 32 + lane];
    }
    rsm[warp][lane] = r0;
    rsm[warp][lane + 32] = r1;
    __syncthreads();
    float inv = 1.f / fmaxf(asum, 1e-16f);
    if (tid < 64) {
        float a2 = 0.f;
        for (int w = 0; w < 8; w++) a2 += rsm[w][tid];
        g_qs[g * 128 + 64 + tid] = a2 * inv;
    } else if (tid < 128) {
        g_qs[g * 128 + (tid - 64)] = sh[tid - 64];
    }
}

// ===================== head =====================
__global__ void __launch_bounds__(128) k_head(const float* __restrict__ W1,
                                              const float* __restrict__ b1,
                                              const float* __restrict__ W2,
                                              const float* __restrict__ b2,
                                              float* __restrict__ outp) {
    __shared__ float sW1[64 * 128];
    __shared__ float sW2[4 * 64];
    __shared__ float sq[128];
    __shared__ float hid[64];
    __shared__ float lg[4];
    int g = blockIdx.x, tid = threadIdx.x;
    for (int i = tid; i < 64 * 128; i += 128) sW1[i] = W1[i];
    for (int i = tid; i < 256; i += 128) sW2[i] = W2[i];
    sq[tid] = g_qs[g * 128 + tid];
    __syncthreads();
    if (tid < 64) {
        float acc = b1[tid];
#pragma unroll 8
        for (int k = 0; k < 128; k++) acc += sq[k] * sW1[tid * 128 + k];
        hid[tid] = fmaxf(acc, 0.f);
    }
    __syncthreads();
    if (tid < 4) {
        float acc = b2[tid];
#pragma unroll
        for (int k = 0; k < 64; k++) acc += hid[k] * sW2[tid * 64 + k];
        lg[tid] = acc;
    }
    __syncthreads();
    if (tid == 0) {
        float m = fmaxf(fmaxf(lg[0], lg[1]), fmaxf(lg[2], lg[3]));
        float sum = expf(lg[0] - m) + expf(lg[1] - m) + expf(lg[2] - m) + expf(lg[3] - m);
        float l = m + logf(sum);
        outp[g * 4 + 0] = lg[0] - l;
        outp[g * 4 + 1] = lg[1] - l;
        outp[g * 4 + 2] = lg[2] - l;
        outp[g * 4 + 3] = lg[3] - l;
    }
}

// ===================== launcher =====================
extern "C" void kernel_launch(void* const* d_in, const int* in_sizes, int n_in,
                              void* d_out, int out_size) {
    const float* x      = (const float*)d_in[0];
    const int*   ei     = (const int*)d_in[1];
    const int*   batch  = (const int*)d_in[2];
    const float* W_mlp  = (const float*)d_in[3];
    const float* b_mlp  = (const float*)d_in[4];
    const float* W_conv = (const float*)d_in[5];
    const float* b_conv = (const float*)d_in[6];
    const float* gWih   = (const float*)d_in[7];
    const float* gWhh   = (const float*)d_in[8];
    const float* gbih   = (const float*)d_in[9];
    const float* gbhh   = (const float*)d_in[10];
    const float* lWih   = (const float*)d_in[11];
    const float* lWhh   = (const float*)d_in[12];
    const float* lbih   = (const float*)d_in[13];
    const float* lbhh   = (const float*)d_in[14];
    const float* W1     = (const float*)d_in[15];
    const float* b1     = (const float*)d_in[16];
    const float* W2     = (const float*)d_in[17];
    const float* b2     = (const float*)d_in[18];

    float *p_out, *p_gx, *p_m0, *p_gg;
    float *p_W0hi, *p_W0lo, *p_b0, *p_Wbhi, *p_Wblo, *p_bzero, *p_WlT, *p_bl;
    cudaGetSymbolAddress((void**)&p_out, g_out);
    cudaGetSymbolAddress((void**)&p_gx, g_gx);
    cudaGetSymbolAddress((void**)&p_m0, g_m0);
    cudaGetSymbolAddress((void**)&p_gg, g_gg);
    cudaGetSymbolAddress((void**)&p_W0hi, g_W0hi);
    cudaGetSymbolAddress((void**)&p_W0lo, g_W0lo);
    cudaGetSymbolAddress((void**)&p_b0, g_b0);
    cudaGetSymbolAddress((void**)&p_Wbhi, g_Wbhi);
    cudaGetSymbolAddress((void**)&p_Wblo, g_Wblo);
    cudaGetSymbolAddress((void**)&p_bzero, g_bzero);
    cudaGetSymbolAddress((void**)&p_WlT, g_WlT);
    cudaGetSymbolAddress((void**)&p_bl, g_bl);

    const int MMA_SMEM = (128 + 128 + 64 + 64) * 36 * 4;   // 55296 B
    cudaFuncSetAttribute((const void*)k_mma<1>, cudaFuncAttributeMaxDynamicSharedMemorySize, MMA_SMEM);
    cudaFuncSetAttribute((const void*)k_mma<4>, cudaFuncAttributeMaxDynamicSharedMemorySize, MMA_SMEM);

    // static side stream + events for graph-captured fork/join
    static cudaStream_t s1 = nullptr;
    static cudaEvent_t ev_fork = nullptr, ev_join = nullptr;
    if (!s1) {
        cudaStreamCreateWithFlags(&s1, cudaStreamNonBlocking);
        cudaEventCreateWithFlags(&ev_fork, cudaEventDisableTiming);
        cudaEventCreateWithFlags(&ev_join, cudaEventDisableTiming);
    }

    // host-launch order arranged so k_mma<1> is index 3 (ncu capture window).
    k_detect<<<256, 256>>>(ei);                          // 0
    cudaEventRecord(ev_fork, 0);
    cudaStreamWaitEvent(s1, ev_fork, 0);

    k_seghist<<<N_EDGES / 256, 256, 0, s1>>>(ei, batch); // 1 (side)
    k_pack<<<128, 256>>>(W_mlp, b_mlp, gWih, gbih, W_conv, b_conv, gWhh,
                         lWih, lWhh, lbih, lbhh);        // 2 (main)
    // [out | gx] = x @ [W_mlp ; Wx]^T + [b_mlp ; b_ih]
    k_mma<1><<<dim3(512, 4), 256, MMA_SMEM>>>(x, x, 32, p_W0hi, p_W0lo, 32, p_b0,
                                              p_out, p_gx, 64, 64, 192, 0);  // 3

    // rest of side-stream CSR chain
    k_scanA<<<256, 256, 0, s1>>>();
    k_scanB<<<1, 256, 0, s1>>>();
    k_scanC<<<256, 256, 0, s1>>>();
    k_fill<<<N_EDGES / 256, 256, 0, s1>>>(ei);
    cudaEventRecord(ev_join, s1);

    // join: gather needs CSR (side) + out (main)
    cudaStreamWaitEvent(0, ev_join, 0);

    for (int s = 0; s < 2; s++) {
        k_gather<<<N_NODES * 16 / 256, 256>>>();
        k_mma<4><<<dim3(512, 4), 256, MMA_SMEM>>>(p_m0, p_out, 64, p_Wbhi, p_Wblo, 128,
                                                  p_bzero, p_gg, p_gg, 256, 256, 256, 1);
        k_gru<<<N_NODES * 64 / 256, 256>>>(gbhh);
    }

    // fused Set2Set: 3 launches, no zero-init kernels (first flag)
    k_s2s<<<256, 256>>>(p_WlT, p_bl, 1);
    k_s2s<<<256, 256>>>(p_WlT, p_bl, 0);
    k_s2s<<<256, 256>>>(p_WlT, p_bl, 0);

    k_head<<<256, 128>>>(W1, b1, W2, b2, (float*)d_out);
}